// round 11
// baseline (speedup 1.0000x reference)
#include <cuda_runtime.h>
#include <cstdint>

// RVQ — mma.sync tf32 (truncated-input) approx GEMM + exact-fp32 refine.
// Deterministic candidate collection (synced prefix-min threshold).
// embeddings: [16, 128, 64, 64] f32 (d_in[0])
// codebooks : [8, 1024, 128]  f32  (d_in[1])
// out       : [16, 128, 64, 64] f32

#define NBOOK   8
#define KCB     1024
#define EDIM    128
#define NROWS   65536
#define TPB     512
#define CHUNK   128
#define NCHUNK  (KCB / CHUNK)
#define EPSM    5e-3f
#define CANDMAX 16
#define PA      132
#define PB      132

// float-index smem offsets
#define OFF_A     0
#define OFF_B0    (OFF_A + 128 * PA)
#define OFF_B1    (OFF_B0 + CHUNK * PB)
#define OFF_NORM  (OFF_B1 + CHUNK * PB)
#define OFF_SA    (OFF_NORM + KCB)
#define OFF_RMIN  (OFF_SA + 128)
#define OFF_CNT   (OFF_RMIN + 128)
#define OFF_BEST  (OFF_CNT + 128)
#define OFF_CAND  (OFF_BEST + 128)
#define SM_FLOATS (OFF_CAND + 128 * CANDMAX)

__device__ __align__(16) float g_quant[NROWS * EDIM];
__device__ float g_norms[NBOOK * KCB];

__device__ __forceinline__ uint32_t smem_u32(const void* p) {
    uint32_t a;
    asm("{ .reg .u64 t; cvta.to.shared.u64 t, %1; cvt.u32.u64 %0, t; }"
        : "=r"(a) : "l"(p));
    return a;
}
__device__ __forceinline__ void cp_async16(uint32_t dst, const void* src) {
    asm volatile("cp.async.cg.shared.global [%0], [%1], 16;"
                 :: "r"(dst), "l"(src) : "memory");
}
#define MMA_TF32(d, a, b0, b1)                                          \
    asm volatile(                                                        \
        "mma.sync.aligned.m16n8k8.row.col.f32.tf32.tf32.f32 "           \
        "{%0,%1,%2,%3}, {%4,%5,%6,%7}, {%8,%9}, {%0,%1,%2,%3};"         \
        : "+f"((d)[0]), "+f"((d)[1]), "+f"((d)[2]), "+f"((d)[3])         \
        : "r"((a)[0]), "r"((a)[1]), "r"((a)[2]), "r"((a)[3]),            \
          "r"(b0), "r"(b1))

// ---------------------------------------------------------------------------
// norms: C_k = sum_e fl(c*c), e ascending (exact chain); float4 loads
// ---------------------------------------------------------------------------
__global__ void k_norms(const float* __restrict__ cb) {
    int idx = blockIdx.x * 64 + threadIdx.x;
    if (idx >= NBOOK * KCB) return;
    const float4* c4 = (const float4*)(cb + (size_t)idx * EDIM);
    float acc = 0.0f;
#pragma unroll 8
    for (int e = 0; e < EDIM / 4; e++) {
        float4 v = __ldg(c4 + e);
        acc = __fadd_rn(acc, __fmul_rn(v.x, v.x));
        acc = __fadd_rn(acc, __fmul_rn(v.y, v.y));
        acc = __fadd_rn(acc, __fmul_rn(v.z, v.z));
        acc = __fadd_rn(acc, __fmul_rn(v.w, v.w));
    }
    g_norms[idx] = acc;
}

// ---------------------------------------------------------------------------
// fused RVQ: one CTA = 128 rows through all 8 books. 512 threads (16 warps).
// Warp grid 4M x 4N; warp tile 32 rows x 32 codes.
// ---------------------------------------------------------------------------
__global__ void __launch_bounds__(TPB, 1)
k_rvq(const float* __restrict__ emb, const float* __restrict__ cb,
      float* __restrict__ out) {
    extern __shared__ float smf[];
    const uint32_t sb = smem_u32(smf);
    const int t = threadIdx.x, lane = t & 31, w = t >> 5;
    const int wm = w & 3, wn = w >> 2;     // 4 M-warps x 4 N-warps
    const int blk = blockIdx.x;
    const int b = blk >> 5;                // batch
    const int hw0 = (blk & 31) << 7;       // hw offset
    const int n0 = blk << 7;               // first global row

    float* A     = smf + OFF_A;
    float* sNorm = smf + OFF_NORM;
    float* sA    = smf + OFF_SA;
    unsigned* rowMinU = (unsigned*)(smf + OFF_RMIN);
    int*   cnt   = (int*)(smf + OFF_CNT);
    int*   sBest = (int*)(smf + OFF_BEST);
    int*   candk = (int*)(smf + OFF_CAND);

    // load residual tile (exact): A[i][e] = emb[b][e][hw0+i]
    for (int v = t; v < 128 * 128; v += TPB) {
        int e = v >> 7, i = v & 127;
        A[i * PA + e] = emb[((size_t)(b * 128 + e) << 12) + hw0 + i];
    }

    // stage book0/chunk0 into B0 (waited at first chunk iteration)
    for (int v = t; v < CHUNK * 32; v += TPB) {
        int code = v >> 5, s = v & 31;
        cp_async16(sb + (OFF_B0 + code * PB + s * 4) * 4,
                   cb + (size_t)code * EDIM + s * 4);
    }
    asm volatile("cp.async.commit_group;" ::: "memory");

    const int frow = lane >> 2;            // 0..7
    const int fcol = lane & 3;             // 0..3

    for (int book = 0; book < NBOOK; book++) {
        const float* cbg = cb + (size_t)book * KCB * EDIM;

        for (int v = t; v < KCB; v += TPB) sNorm[v] = g_norms[book * KCB + v];
        if (t < 128) {
            cnt[t] = 0;
            rowMinU[t] = 0x7f7fffffu;
            // A = ||r||^2 exact chain (e ascending, fl(mul) then fl(add))
            float acc = 0.0f;
            const float* ar = &A[t * PA];
            for (int e = 0; e < EDIM; e++)
                acc = __fadd_rn(acc, __fmul_rn(ar[e], ar[e]));
            sA[t] = acc;
        }
        __syncthreads();

        float arg[2][2];
#pragma unroll
        for (int mt = 0; mt < 2; mt++)
#pragma unroll
            for (int h = 0; h < 2; h++)
                arg[mt][h] = sA[wm * 32 + mt * 16 + frow + h * 8];

        for (int c = 0; c < NCHUNK; c++) {
            const float* Bc = smf + ((c & 1) ? OFF_B1 : OFF_B0);

            // publish buf[c&1]; also orders MMA(c-1) before overwrite below
            asm volatile("cp.async.wait_group 0;" ::: "memory");
            __syncthreads();

            // prefetch next: (book, c+1) or (book+1, 0); lands during MMA(c)
            bool has_next = !(book == NBOOK - 1 && c == NCHUNK - 1);
            if (has_next) {
                const float* srcn = (c + 1 < NCHUNK)
                    ? cbg + (size_t)(c + 1) * CHUNK * EDIM
                    : cbg + (size_t)KCB * EDIM;   // next book chunk 0
                int nboff = ((c + 1) & 1) ? OFF_B1 : OFF_B0;
                for (int v = t; v < CHUNK * 32; v += TPB) {
                    int code = v >> 5, s = v & 31;
                    cp_async16(sb + (nboff + code * PB + s * 4) * 4,
                               srcn + (size_t)code * EDIM + s * 4);
                }
                asm volatile("cp.async.commit_group;" ::: "memory");
            }

            // ---- tf32 MMA (truncated fp32 inputs): 2 m16 x 4 n8 x 16 k8 ----
            float d[2][4][4];
#pragma unroll
            for (int mt = 0; mt < 2; mt++)
#pragma unroll
                for (int nt = 0; nt < 4; nt++)
#pragma unroll
                    for (int q = 0; q < 4; q++) d[mt][nt][q] = 0.0f;

#pragma unroll 4
            for (int ks = 0; ks < 16; ks++) {
                int k0 = ks * 8;
                uint32_t a[2][4];
#pragma unroll
                for (int mt = 0; mt < 2; mt++) {
                    int r0 = wm * 32 + mt * 16 + frow;
                    a[mt][0] = __float_as_uint(A[r0 * PA + k0 + fcol]);
                    a[mt][1] = __float_as_uint(A[(r0 + 8) * PA + k0 + fcol]);
                    a[mt][2] = __float_as_uint(A[r0 * PA + k0 + fcol + 4]);
                    a[mt][3] = __float_as_uint(A[(r0 + 8) * PA + k0 + fcol + 4]);
                }
#pragma unroll
                for (int nt = 0; nt < 4; nt++) {
                    int cl = wn * 32 + nt * 8 + frow;
                    uint32_t b0 = __float_as_uint(Bc[cl * PB + k0 + fcol]);
                    uint32_t b1 = __float_as_uint(Bc[cl * PB + k0 + fcol + 4]);
                    MMA_TF32(d[0][nt], a[0], b0, b1);
                    MMA_TF32(d[1][nt], a[1], b0, b1);
                }
            }

            // ---- epilogue: d_app = fma(-2,S,A) + C; row-min update ----
            int kchunk = c * CHUNK + wn * 32;
#pragma unroll
            for (int mt = 0; mt < 2; mt++)
#pragma unroll
                for (int nt = 0; nt < 4; nt++)
#pragma unroll
                    for (int q = 0; q < 4; q++) {
                        int k = kchunk + nt * 8 + 2 * fcol + (q & 1);
                        d[mt][nt][q] = __fadd_rn(
                            __fmaf_rn(-2.0f, d[mt][nt][q], arg[mt][q >> 1]),
                            sNorm[k]);
                    }
#pragma unroll
            for (int mt = 0; mt < 2; mt++)
#pragma unroll
                for (int h = 0; h < 2; h++) {
                    float lm = 3.4e38f;
#pragma unroll
                    for (int nt = 0; nt < 4; nt++)
                        lm = fminf(lm, fminf(d[mt][nt][h * 2],
                                             d[mt][nt][h * 2 + 1]));
                    int row = wm * 32 + mt * 16 + frow + h * 8;
                    atomicMin(&rowMinU[row], __float_as_uint(lm));
                }
            // DETERMINISM: threshold must be the synced prefix-min, not a
            // racy read (R10 post-timing divergence). This barrier makes the
            // candidate set a pure function of the inputs.
            __syncthreads();

            // ---- collect candidates within margin of prefix-min ----
#pragma unroll
            for (int mt = 0; mt < 2; mt++)
#pragma unroll
                for (int h = 0; h < 2; h++) {
                    int row = wm * 32 + mt * 16 + frow + h * 8;
                    float thr = __uint_as_float(rowMinU[row]) + EPSM;
#pragma unroll
                    for (int nt = 0; nt < 4; nt++)
#pragma unroll
                        for (int qq = 0; qq < 2; qq++) {
                            if (d[mt][nt][h * 2 + qq] <= thr) {
                                int k = kchunk + nt * 8 + 2 * fcol + qq;
                                int p = atomicAdd(&cnt[row], 1);
                                if (p < CANDMAX)
                                    candk[row * CANDMAX + p] = k;
                            }
                        }
                }
        }
        __syncthreads();   // all collects done

        // ---- exact refine: thread t owns row t (chains identical to R1) ----
        if (t < 128) {
            int n = cnt[t];
            float Arow = sA[t];
            float bd = 3.4e38f; int bk = 0x7fffffff;
            const float* ar = &A[t * PA];
            if (n <= CANDMAX) {
                for (int i = 0; i < n; i++) {
                    int k = candk[t * CANDMAX + i];
                    const float* cp = cbg + (size_t)k * EDIM;
                    float dot = 0.0f;
#pragma unroll 8
                    for (int e = 0; e < EDIM; e += 4) {
                        float4 c4 = __ldg((const float4*)(cp + e));
                        dot = __fmaf_rn(ar[e], c4.x, dot);
                        dot = __fmaf_rn(ar[e + 1], c4.y, dot);
                        dot = __fmaf_rn(ar[e + 2], c4.z, dot);
                        dot = __fmaf_rn(ar[e + 3], c4.w, dot);
                    }
                    float dd = __fadd_rn(__fsub_rn(Arow, 2.0f * dot), sNorm[k]);
                    if (dd < bd || (dd == bd && k < bk)) { bd = dd; bk = k; }
                }
            } else {   // safety fallback: exact full scan
                for (int k = 0; k < KCB; k++) {
                    const float* cp = cbg + (size_t)k * EDIM;
                    float dot = 0.0f;
                    for (int e = 0; e < EDIM; e += 4) {
                        float4 c4 = __ldg((const float4*)(cp + e));
                        dot = __fmaf_rn(ar[e], c4.x, dot);
                        dot = __fmaf_rn(ar[e + 1], c4.y, dot);
                        dot = __fmaf_rn(ar[e + 2], c4.z, dot);
                        dot = __fmaf_rn(ar[e + 3], c4.w, dot);
                    }
                    float dd = __fadd_rn(__fsub_rn(Arow, 2.0f * dot), sNorm[k]);
                    if (dd < bd) { bd = dd; bk = k; }
                }
            }
            sBest[t] = bk;
        }
        __syncthreads();

        // ---- res -= dec (SMEM, exact); quant += dec (global, exact) ----
        for (int v = t; v < 128 * 32; v += TPB) {
            int row = v >> 5, e4 = (v & 31) << 2;
            int k = sBest[row];
            float4 dec = __ldg((const float4*)(cbg + (size_t)k * EDIM + e4));
            float* rp = &A[row * PA + e4];
            rp[0] = __fsub_rn(rp[0], dec.x);
            rp[1] = __fsub_rn(rp[1], dec.y);
            rp[2] = __fsub_rn(rp[2], dec.z);
            rp[3] = __fsub_rn(rp[3], dec.w);
            float4* qp = (float4*)&g_quant[(size_t)(n0 + row) * EDIM + e4];
            if (book == 0) {
                *qp = dec;
            } else {
                float4 q = *qp;
                q.x = __fadd_rn(q.x, dec.x); q.y = __fadd_rn(q.y, dec.y);
                q.z = __fadd_rn(q.z, dec.z); q.w = __fadd_rn(q.w, dec.w);
                *qp = q;
            }
        }
        __syncthreads();
    }

    // ---- output: quant [row][e] -> out NCHW, warp-tiled smem transpose ----
    {
        float* ts = smf + OFF_B0 + w * (32 * 33);
        int i0 = (w & 3) * 32, e0 = (w >> 2) * 32;
#pragma unroll 4
        for (int r = 0; r < 32; r++)
            ts[r * 33 + lane] = g_quant[(size_t)(n0 + i0 + r) * EDIM + e0 + lane];
        __syncwarp();
#pragma unroll 4
        for (int r = 0; r < 32; r++)
            out[((size_t)(b * 128 + e0 + r) << 12) + hw0 + i0 + lane] =
                ts[lane * 33 + r];
    }
}

// ---------------------------------------------------------------------------
extern "C" void kernel_launch(void* const* d_in, const int* in_sizes, int n_in,
                              void* d_out, int out_size) {
    (void)in_sizes; (void)n_in; (void)out_size;
    const float* emb = (const float*)d_in[0];
    const float* cb  = (const float*)d_in[1];
    float* out = (float*)d_out;

    const int smem_bytes = SM_FLOATS * 4;
    cudaFuncSetAttribute(k_rvq, cudaFuncAttributeMaxDynamicSharedMemorySize,
                         smem_bytes);
    k_norms<<<NBOOK * KCB / 64, 64>>>(cb);
    k_rvq<<<NROWS / 128, TPB, smem_bytes>>>(emb, cb, out);
}

// round 13
// speedup vs baseline: 12.0911x; 12.0911x over previous
#include <cuda_runtime.h>
#include <cstdint>

// RVQ — mma.sync tf32 approx GEMM + exact-fp32 refine (R8-validated core).
// quant reconstructed at the end from per-book indices (no g_quant traffic).
// embeddings: [16, 128, 64, 64] f32 (d_in[0])
// codebooks : [8, 1024, 128]  f32  (d_in[1])
// out       : [16, 128, 64, 64] f32

#define NBOOK   8
#define KCB     1024
#define EDIM    128
#define NROWS   65536
#define TPB     512
#define CHUNK   128
#define NCHUNK  (KCB / CHUNK)
#define EPSM    1e-3f
#define CANDMAX 16
#define PA      132
#define PB      132

// float-index smem offsets
#define OFF_A     0
#define OFF_B0    (OFF_A + 128 * PA)       // also: final quant tile (pitch 132)
#define OFF_B1    (OFF_B0 + CHUNK * PB)    // also: transpose scratch
#define OFF_NORM  (OFF_B1 + CHUNK * PB)
#define OFF_SA    (OFF_NORM + KCB)
#define OFF_RMIN  (OFF_SA + 128)
#define OFF_CNT   (OFF_RMIN + 128)
#define OFF_BEST8 (OFF_CNT + 128)          // [8][128] ints
#define OFF_CAND  (OFF_BEST8 + 8 * 128)
#define SM_FLOATS (OFF_CAND + 128 * CANDMAX)

__device__ float g_norms[NBOOK * KCB];

__device__ __forceinline__ uint32_t smem_u32(const void* p) {
    uint32_t a;
    asm("{ .reg .u64 t; cvta.to.shared.u64 t, %1; cvt.u32.u64 %0, t; }"
        : "=r"(a) : "l"(p));
    return a;
}
__device__ __forceinline__ void cp_async16(uint32_t dst, const void* src) {
    asm volatile("cp.async.cg.shared.global [%0], [%1], 16;"
                 :: "r"(dst), "l"(src) : "memory");
}
#define MMA_TF32(d, a, b0, b1)                                          \
    asm volatile(                                                        \
        "mma.sync.aligned.m16n8k8.row.col.f32.tf32.tf32.f32 "           \
        "{%0,%1,%2,%3}, {%4,%5,%6,%7}, {%8,%9}, {%0,%1,%2,%3};"         \
        : "+f"((d)[0]), "+f"((d)[1]), "+f"((d)[2]), "+f"((d)[3])         \
        : "r"((a)[0]), "r"((a)[1]), "r"((a)[2]), "r"((a)[3]),            \
          "r"(b0), "r"(b1))

// ---------------------------------------------------------------------------
// norms: C_k = sum_e fl(c*c), e ascending (exact chain); float4 loads
// ---------------------------------------------------------------------------
__global__ void k_norms(const float* __restrict__ cb) {
    int idx = blockIdx.x * 64 + threadIdx.x;
    if (idx >= NBOOK * KCB) return;
    const float4* c4 = (const float4*)(cb + (size_t)idx * EDIM);
    float acc = 0.0f;
#pragma unroll 8
    for (int e = 0; e < EDIM / 4; e++) {
        float4 v = __ldg(c4 + e);
        acc = __fadd_rn(acc, __fmul_rn(v.x, v.x));
        acc = __fadd_rn(acc, __fmul_rn(v.y, v.y));
        acc = __fadd_rn(acc, __fmul_rn(v.z, v.z));
        acc = __fadd_rn(acc, __fmul_rn(v.w, v.w));
    }
    g_norms[idx] = acc;
}

// ---------------------------------------------------------------------------
// fused RVQ: one CTA = 128 rows through all 8 books. 512 threads (16 warps).
// Warp grid 4M x 4N; warp tile 32 rows x 32 codes. Mainloop = R8 verbatim.
// ---------------------------------------------------------------------------
__global__ void __launch_bounds__(TPB, 1)
k_rvq(const float* __restrict__ emb, const float* __restrict__ cb,
      float* __restrict__ out) {
    extern __shared__ float smf[];
    const uint32_t sb = smem_u32(smf);
    const int t = threadIdx.x, lane = t & 31, w = t >> 5;
    const int wm = w & 3, wn = w >> 2;     // 4 M-warps x 4 N-warps
    const int blk = blockIdx.x;
    const int b = blk >> 5;                // batch
    const int hw0 = (blk & 31) << 7;       // hw offset
    const int n0 = blk << 7;               // first global row (unused for out)

    float* A     = smf + OFF_A;
    float* sNorm = smf + OFF_NORM;
    float* sA    = smf + OFF_SA;
    unsigned* rowMinU = (unsigned*)(smf + OFF_RMIN);
    int*   cnt   = (int*)(smf + OFF_CNT);
    int*   sBest8 = (int*)(smf + OFF_BEST8);
    int*   candk = (int*)(smf + OFF_CAND);
    (void)n0;

    // load residual tile (exact): A[i][e] = emb[b][e][hw0+i]
    for (int v = t; v < 128 * 128; v += TPB) {
        int e = v >> 7, i = v & 127;
        A[i * PA + e] = emb[((size_t)(b * 128 + e) << 12) + hw0 + i];
    }
    __syncthreads();

    const int frow = lane >> 2;            // 0..7
    const int fcol = lane & 3;             // 0..3

    for (int book = 0; book < NBOOK; book++) {
        const float* cbg = cb + (size_t)book * KCB * EDIM;

        for (int v = t; v < KCB; v += TPB) sNorm[v] = g_norms[book * KCB + v];
        if (t < 128) {
            cnt[t] = 0;
            rowMinU[t] = 0x7f7fffffu;
            // A = ||r||^2 exact chain (e ascending, fl(mul) then fl(add))
            float acc = 0.0f;
            const float* ar = &A[t * PA];
            for (int e = 0; e < EDIM; e++)
                acc = __fadd_rn(acc, __fmul_rn(ar[e], ar[e]));
            sA[t] = acc;
        }
        __syncthreads();

        float arg[2][2];
#pragma unroll
        for (int mt = 0; mt < 2; mt++)
#pragma unroll
            for (int h = 0; h < 2; h++)
                arg[mt][h] = sA[wm * 32 + mt * 16 + frow + h * 8];

        // prologue: stage chunk 0 into B0 (R8 structure: per book)
        for (int v = t; v < CHUNK * 32; v += TPB) {
            int code = v >> 5, s = v & 31;
            cp_async16(sb + (OFF_B0 + code * PB + s * 4) * 4,
                       cbg + (size_t)code * EDIM + s * 4);
        }
        asm volatile("cp.async.commit_group;" ::: "memory");
        asm volatile("cp.async.wait_group 0;" ::: "memory");
        __syncthreads();

        for (int c = 0; c < NCHUNK; c++) {
            const float* Bc = smf + ((c & 1) ? OFF_B1 : OFF_B0);
            if (c + 1 < NCHUNK) {   // prefetch next chunk
                int nboff = ((c + 1) & 1) ? OFF_B1 : OFF_B0;
                const float* srcn = cbg + (size_t)(c + 1) * CHUNK * EDIM;
                for (int v = t; v < CHUNK * 32; v += TPB) {
                    int code = v >> 5, s = v & 31;
                    cp_async16(sb + (nboff + code * PB + s * 4) * 4,
                               srcn + (size_t)code * EDIM + s * 4);
                }
                asm volatile("cp.async.commit_group;" ::: "memory");
            }

            // ---- tf32 MMA (truncated fp32 inputs): 2 m16 x 4 n8 x 16 k8 ----
            float d[2][4][4];
#pragma unroll
            for (int mt = 0; mt < 2; mt++)
#pragma unroll
                for (int nt = 0; nt < 4; nt++)
#pragma unroll
                    for (int q = 0; q < 4; q++) d[mt][nt][q] = 0.0f;

#pragma unroll 4
            for (int ks = 0; ks < 16; ks++) {
                int k0 = ks * 8;
                uint32_t a[2][4];
#pragma unroll
                for (int mt = 0; mt < 2; mt++) {
                    int r0 = wm * 32 + mt * 16 + frow;
                    a[mt][0] = __float_as_uint(A[r0 * PA + k0 + fcol]);
                    a[mt][1] = __float_as_uint(A[(r0 + 8) * PA + k0 + fcol]);
                    a[mt][2] = __float_as_uint(A[r0 * PA + k0 + fcol + 4]);
                    a[mt][3] = __float_as_uint(A[(r0 + 8) * PA + k0 + fcol + 4]);
                }
#pragma unroll
                for (int nt = 0; nt < 4; nt++) {
                    int cl = wn * 32 + nt * 8 + frow;
                    uint32_t b0 = __float_as_uint(Bc[cl * PB + k0 + fcol]);
                    uint32_t b1 = __float_as_uint(Bc[cl * PB + k0 + fcol + 4]);
                    MMA_TF32(d[0][nt], a[0], b0, b1);
                    MMA_TF32(d[1][nt], a[1], b0, b1);
                }
            }

            // ---- epilogue: d_app = fma(-2,S,A) + C; row-min update ----
            int kchunk = c * CHUNK + wn * 32;
#pragma unroll
            for (int mt = 0; mt < 2; mt++)
#pragma unroll
                for (int nt = 0; nt < 4; nt++)
#pragma unroll
                    for (int q = 0; q < 4; q++) {
                        int k = kchunk + nt * 8 + 2 * fcol + (q & 1);
                        d[mt][nt][q] = __fadd_rn(
                            __fmaf_rn(-2.0f, d[mt][nt][q], arg[mt][q >> 1]),
                            sNorm[k]);
                    }
#pragma unroll
            for (int mt = 0; mt < 2; mt++)
#pragma unroll
                for (int h = 0; h < 2; h++) {
                    float lm = 3.4e38f;
#pragma unroll
                    for (int nt = 0; nt < 4; nt++)
                        lm = fminf(lm, fminf(d[mt][nt][h * 2],
                                             d[mt][nt][h * 2 + 1]));
                    int row = wm * 32 + mt * 16 + frow + h * 8;
                    atomicMin(&rowMinU[row], __float_as_uint(lm));
                }
            __syncthreads();

            // ---- collect candidates within margin of prefix-min ----
#pragma unroll
            for (int mt = 0; mt < 2; mt++)
#pragma unroll
                for (int h = 0; h < 2; h++) {
                    int row = wm * 32 + mt * 16 + frow + h * 8;
                    float thr = __uint_as_float(rowMinU[row]) + EPSM;
#pragma unroll
                    for (int nt = 0; nt < 4; nt++)
#pragma unroll
                        for (int qq = 0; qq < 2; qq++) {
                            if (d[mt][nt][h * 2 + qq] <= thr) {
                                int k = kchunk + nt * 8 + 2 * fcol + qq;
                                int p = atomicAdd(&cnt[row], 1);
                                if (p < CANDMAX)
                                    candk[row * CANDMAX + p] = k;
                            }
                        }
                }
            if (c + 1 < NCHUNK)
                asm volatile("cp.async.wait_group 0;" ::: "memory");
            __syncthreads();
        }

        // ---- exact refine: thread t owns row t (chains identical to R1) ----
        if (t < 128) {
            int n = cnt[t];
            float Arow = sA[t];
            float bd = 3.4e38f; int bk = 0x7fffffff;
            const float* ar = &A[t * PA];
            if (n <= CANDMAX) {
                for (int i = 0; i < n; i++) {
                    int k = candk[t * CANDMAX + i];
                    const float* cp = cbg + (size_t)k * EDIM;
                    float dot = 0.0f;
#pragma unroll 8
                    for (int e = 0; e < EDIM; e += 4) {
                        float4 c4 = __ldg((const float4*)(cp + e));
                        dot = __fmaf_rn(ar[e], c4.x, dot);
                        dot = __fmaf_rn(ar[e + 1], c4.y, dot);
                        dot = __fmaf_rn(ar[e + 2], c4.z, dot);
                        dot = __fmaf_rn(ar[e + 3], c4.w, dot);
                    }
                    float dd = __fadd_rn(__fsub_rn(Arow, 2.0f * dot), sNorm[k]);
                    if (dd < bd || (dd == bd && k < bk)) { bd = dd; bk = k; }
                }
            } else {   // safety fallback: exact full scan
                for (int k = 0; k < KCB; k++) {
                    const float* cp = cbg + (size_t)k * EDIM;
                    float dot = 0.0f;
                    for (int e = 0; e < EDIM; e += 4) {
                        float4 c4 = __ldg((const float4*)(cp + e));
                        dot = __fmaf_rn(ar[e], c4.x, dot);
                        dot = __fmaf_rn(ar[e + 1], c4.y, dot);
                        dot = __fmaf_rn(ar[e + 2], c4.z, dot);
                        dot = __fmaf_rn(ar[e + 3], c4.w, dot);
                    }
                    float dd = __fadd_rn(__fsub_rn(Arow, 2.0f * dot), sNorm[k]);
                    if (dd < bd) { bd = dd; bk = k; }
                }
            }
            sBest8[book * 128 + t] = bk;
        }
        __syncthreads();

        // ---- res -= dec (SMEM, exact). Skipped for last book (res dead). ----
        if (book < NBOOK - 1) {
            for (int v = t; v < 128 * 32; v += TPB) {
                int row = v >> 5, e4 = (v & 31) << 2;
                int k = sBest8[book * 128 + row];
                float4 dec = __ldg((const float4*)(cbg + (size_t)k * EDIM + e4));
                float* rp = &A[row * PA + e4];
                rp[0] = __fsub_rn(rp[0], dec.x);
                rp[1] = __fsub_rn(rp[1], dec.y);
                rp[2] = __fsub_rn(rp[2], dec.z);
                rp[3] = __fsub_rn(rp[3], dec.w);
            }
        }
        __syncthreads();
    }

    // ---- quant reconstruction: q = ((dec0+dec1)+...+dec7), exact order ----
    // Written into the dead B0 region as a [128][PA] tile.
    float* Q = smf + OFF_B0;
    for (int v = t; v < 128 * 32; v += TPB) {
        int row = v >> 5, e4 = (v & 31) << 2;
        float4 q = __ldg((const float4*)(
            cb + ((size_t)sBest8[row]) * EDIM + e4));   // book 0
#pragma unroll
        for (int bkk = 1; bkk < NBOOK; bkk++) {
            int k = sBest8[bkk * 128 + row];
            float4 dv = __ldg((const float4*)(
                cb + ((size_t)bkk * KCB + k) * EDIM + e4));
            q.x = __fadd_rn(q.x, dv.x); q.y = __fadd_rn(q.y, dv.y);
            q.z = __fadd_rn(q.z, dv.z); q.w = __fadd_rn(q.w, dv.w);
        }
        *(float4*)&Q[row * PA + e4] = q;
    }
    __syncthreads();

    // ---- output: Q [row][e] (smem) -> out NCHW, warp-tiled transpose ----
    {
        float* ts = smf + OFF_B1 + w * (32 * 33);
        int i0 = (w & 3) * 32, e0 = (w >> 2) * 32;
#pragma unroll 4
        for (int r = 0; r < 32; r++)
            ts[r * 33 + lane] = Q[(i0 + r) * PA + e0 + lane];
        __syncwarp();
#pragma unroll 4
        for (int r = 0; r < 32; r++)
            out[((size_t)(b * 128 + e0 + r) << 12) + hw0 + i0 + lane] =
                ts[lane * 33 + r];
    }
}

// ---------------------------------------------------------------------------
extern "C" void kernel_launch(void* const* d_in, const int* in_sizes, int n_in,
                              void* d_out, int out_size) {
    (void)in_sizes; (void)n_in; (void)out_size;
    const float* emb = (const float*)d_in[0];
    const float* cb  = (const float*)d_in[1];
    float* out = (float*)d_out;

    const int smem_bytes = SM_FLOATS * 4;
    cudaFuncSetAttribute(k_rvq, cudaFuncAttributeMaxDynamicSharedMemorySize,
                         smem_bytes);
    k_norms<<<NBOOK * KCB / 64, 64>>>(cb);
    k_rvq<<<NROWS / 128, TPB, smem_bytes>>>(emb, cb, out);
}